// round 14
// baseline (speedup 1.0000x reference)
#include <cuda_runtime.h>
#include <cuda_bf16.h>
#include <stdint.h>

// ---------------- problem constants ----------------
#define DV      512
#define NKSUB   4            // 512 / 128 int8 k-subtiles
#define MT      128          // query rows per m-tile
#define NMT     16           // 2048 / 128
#define NC      128          // db rows per chunk
#define NCHUNK  782          // ceil(100000/128)
#define NDB     100000
#define NDB_PAD (NCHUNK * NC)
#define SPLITS  37           // 16*37 = 592 CTAs = 4 waves of 148
#define KSEL    10
#define TILE_BYTES 16384     // [128 rows x 128 k] int8, SW128-swizzled
#define NLIST   8

// smem layout
#define SM_MBAR    0
#define SM_SCALE   1024                              // 4 x 512 B db-scale buffers
#define SM_Q       3072                              // 4 x 16 KB = 64 KB
#define SM_DB      (SM_Q + NKSUB * TILE_BYTES)       // 68608
#define NSTAGE     8
#define SMEM_TOTAL (SM_DB + NSTAGE * TILE_BYTES)     // 199680 (< 227KB cap)

#define MB_DBFULL(s)  (SM_MBAR + 8 * (s))            // 8
#define MB_DBDONE(s)  (SM_MBAR + 64 + 8 * (s))       // 8
#define MB_QFULL      (SM_MBAR + 128)

// ---------------- global scratch (no allocs allowed) ----------------
__device__ __align__(1024) unsigned char g_qn[(size_t)NMT * NKSUB * TILE_BYTES];      // 1 MB int8
__device__ __align__(1024) unsigned char g_dbn[(size_t)NCHUNK * NKSUB * TILE_BYTES];  // ~51 MB int8
__device__ float g_qs[NMT * MT];                                                      // q row scales
__device__ __align__(16) float g_dbs[NDB_PAD];                                        // db row scales
__device__ float g_topk[(size_t)NMT * SPLITS * MT * KSEL];                            // 3 MB

// ---------------- PTX helpers (all base-sm_100-safe; no tcgen05) ----------------
__device__ __forceinline__ uint32_t smem_u32(const void* p) {
    return (uint32_t)__cvta_generic_to_shared(p);
}
__device__ __forceinline__ uint32_t elect1() {
    uint32_t p;
    asm volatile("{\n\t.reg .pred P;\n\telect.sync _|P, 0xffffffff;\n\tselp.b32 %0,1,0,P;\n\t}" : "=r"(p));
    return p;
}
__device__ __forceinline__ void mbar_init(uint32_t a, uint32_t cnt) {
    asm volatile("mbarrier.init.shared.b64 [%0], %1;" :: "r"(a), "r"(cnt) : "memory");
}
__device__ __forceinline__ void mbar_expect_tx(uint32_t a, uint32_t bytes) {
    asm volatile("mbarrier.arrive.expect_tx.shared.b64 _, [%0], %1;" :: "r"(a), "r"(bytes) : "memory");
}
__device__ __forceinline__ void mbar_arrive(uint32_t a) {
    asm volatile("mbarrier.arrive.shared.b64 _, [%0];" :: "r"(a) : "memory");
}
__device__ __forceinline__ void mbar_wait(uint32_t a, uint32_t parity) {
    asm volatile(
        "{\n\t.reg .pred P;\n"
        "WL%=:\n\t"
        "mbarrier.try_wait.parity.acquire.cta.shared::cta.b64 P, [%0], %1, 0x989680;\n\t"
        "@P bra.uni WD%=;\n\t"
        "bra.uni WL%=;\n"
        "WD%=:\n\t}"
        :: "r"(a), "r"(parity) : "memory");
}
__device__ __forceinline__ void bulk_g2s(uint32_t dst, const void* src, uint32_t bytes, uint32_t mbar) {
    asm volatile(
        "cp.async.bulk.shared::cluster.global.mbarrier::complete_tx::bytes [%0], [%1], %2, [%3];"
        :: "r"(dst), "l"(src), "r"(bytes), "r"(mbar) : "memory");
}
__device__ __forceinline__ void ldsm_x4(uint32_t* r, uint32_t addr) {
    asm volatile("ldmatrix.sync.aligned.m8n8.x4.shared.b16 {%0,%1,%2,%3}, [%4];"
                 : "=r"(r[0]), "=r"(r[1]), "=r"(r[2]), "=r"(r[3]) : "r"(addr));
}
// int8 mma: m16n8k32.s8 fragments are byte-identical to m16n8k16.b16 fragments.
__device__ __forceinline__ void mma16832_s8(int* d, const uint32_t* a, uint32_t b0, uint32_t b1) {
    asm volatile(
        "mma.sync.aligned.m16n8k32.row.col.s32.s8.s8.s32 "
        "{%0,%1,%2,%3}, {%4,%5,%6,%7}, {%8,%9}, {%0,%1,%2,%3};"
        : "+r"(d[0]), "+r"(d[1]), "+r"(d[2]), "+r"(d[3])
        : "r"(a[0]), "r"(a[1]), "r"(a[2]), "r"(a[3]), "r"(b0), "r"(b1));
}

__device__ __forceinline__ void topk_insert(float (&t)[KSEL], float v) {
    if (v > t[KSEL - 1]) {
        t[KSEL - 1] = v;
#pragma unroll
        for (int i = KSEL - 1; i > 0; --i) {
            if (t[i] > t[i - 1]) { float tmp = t[i - 1]; t[i - 1] = t[i]; t[i] = tmp; }
        }
    }
}

// ---------------- prep: normalize + per-row int8 quantize, tiled + SW128 pre-swizzled ----------------
__global__ void knn_prep_kernel(const float* __restrict__ src, int which,
                                int rows_pad, int rows_valid) {
    int gw = (blockIdx.x * blockDim.x + threadIdx.x) >> 5;
    int lane = threadIdx.x & 31;
    if (gw >= rows_pad) return;
    int tile = gw >> 7;
    int tr = gw & 127;
    unsigned char* tbase = (which ? g_dbn : g_qn) + (size_t)tile * (NKSUB * TILE_BYTES);

    int c0 = lane * 16;
    int ks = c0 >> 7;
    uint32_t off = (uint32_t)(tr * 128 + (c0 & 127));
    off ^= (off >> 3) & 0x70;         // SW128
    unsigned char* dst = tbase + (size_t)ks * TILE_BYTES + off;

    if (gw >= rows_valid) {           // zero pad (db only)
        *(uint4*)dst = make_uint4(0u, 0u, 0u, 0u);
        if (lane == 0) g_dbs[gw] = 0.f;
        return;
    }

    const float4* row = (const float4*)(src + (size_t)gw * DV);
    float4 v[4];
    float ss = 0.f, am = 0.f;
#pragma unroll
    for (int i = 0; i < 4; i++) {
        v[i] = row[i * 32 + lane];
        ss += v[i].x * v[i].x + v[i].y * v[i].y + v[i].z * v[i].z + v[i].w * v[i].w;
        am = fmaxf(am, fmaxf(fmaxf(fabsf(v[i].x), fabsf(v[i].y)), fmaxf(fabsf(v[i].z), fabsf(v[i].w))));
    }
#pragma unroll
    for (int o = 16; o; o >>= 1) {
        ss += __shfl_xor_sync(0xffffffffu, ss, o);
        am = fmaxf(am, __shfl_xor_sync(0xffffffffu, am, o));
    }
    float rn = rsqrtf(ss);
    rn = rn * (1.5f - 0.5f * ss * rn * rn);
    float inv = 127.0f / fmaxf(am, 1e-20f);

    uint32_t w[4];
#pragma unroll
    for (int i = 0; i < 4; i++) {
        int q0 = __float2int_rn(v[i].x * inv);
        int q1 = __float2int_rn(v[i].y * inv);
        int q2 = __float2int_rn(v[i].z * inv);
        int q3 = __float2int_rn(v[i].w * inv);
        w[i] = (q0 & 0xff) | ((q1 & 0xff) << 8) | ((q2 & 0xff) << 16) | ((q3 & 0xff) << 24);
    }
    *(uint4*)dst = make_uint4(w[0], w[1], w[2], w[3]);
    if (lane == 0) {
        float sc = am * rn / 127.0f;
        if (which) g_dbs[gw] = sc; else g_qs[gw] = sc;
    }
}

// ---------------- main GEMM (mma.sync s8) + fused streaming top-k ----------------
// grid (NMT, SPLITS), 288 threads: warps 0-7 compute (4m x 2n), warp 8 producer.
// R12: int-domain group prune in the fold epilogue.
__global__ void __launch_bounds__(288, 1) knn_gemm_kernel() {
    extern __shared__ unsigned char smem[];
    uint32_t sb = smem_u32(smem);
    int tid = threadIdx.x;
    int wid = tid >> 5;
    int lane = tid & 31;
    int mt = blockIdx.x;
    int sp = blockIdx.y;
    int nloc = (NCHUNK - sp + SPLITS - 1) / SPLITS;

    if (tid == 0) {
#pragma unroll
        for (int s = 0; s < NSTAGE; s++) { mbar_init(sb + MB_DBFULL(s), 1); mbar_init(sb + MB_DBDONE(s), 8); }
        mbar_init(sb + MB_QFULL, 1);
    }
    __syncthreads();

    if (wid == 8) {
        // -------- producer --------
        if (elect1()) {
            const unsigned char* qg = g_qn + (size_t)mt * (NKSUB * TILE_BYTES);
            mbar_expect_tx(sb + MB_QFULL, NKSUB * TILE_BYTES);
#pragma unroll
            for (int j = 0; j < NKSUB; j++)
                bulk_g2s(sb + SM_Q + j * TILE_BYTES, qg + (size_t)j * TILE_BYTES, TILE_BYTES, sb + MB_QFULL);
            int kk = 0;
            for (int i = 0; i < nloc; i++) {
                int c = sp + i * SPLITS;
                const unsigned char* dg = g_dbn + (size_t)c * (NKSUB * TILE_BYTES);
                for (int j = 0; j < NKSUB; j++, kk++) {
                    int s = kk & (NSTAGE - 1);
                    if (kk >= NSTAGE) mbar_wait(sb + MB_DBDONE(s), ((kk >> 3) & 1) ^ 1);
                    mbar_expect_tx(sb + MB_DBFULL(s), TILE_BYTES + (j == 0 ? 512 : 0));
                    bulk_g2s(sb + SM_DB + s * TILE_BYTES, dg + (size_t)j * TILE_BYTES, TILE_BYTES,
                             sb + MB_DBFULL(s));
                    if (j == 0)  // chunk's 128 db row scales -> 4-deep buffer
                        bulk_g2s(sb + SM_SCALE + (i & 3) * 512, g_dbs + c * NC, 512, sb + MB_DBFULL(s));
                }
            }
        }
        return;
    }

    // -------- compute warps --------
    int wm = (wid >> 1) * 32;
    int wn = (wid & 1) * 64;
    int mat = lane >> 3, mrow = lane & 7;
    uint32_t xm = (uint32_t)(mrow * 16);                 // SW128 xor mask
    int a_r0 = wm + (mat & 1) * 8 + mrow;
    uint32_t a_k2 = (uint32_t)((mat >> 1) * 16);
    uint32_t qb0 = sb + SM_Q + (uint32_t)(a_r0 * 128);
    uint32_t qb1 = qb0 + 16 * 128;
    int b_n = wn + (mat >> 1) * 8 + mrow;
    uint32_t b_k2 = (uint32_t)((mat & 1) * 16);
    uint32_t dbrow = (uint32_t)(b_n * 128);

    // q row scales for this thread's 4 owned rows
    float qsc[4];
#pragma unroll
    for (int mi = 0; mi < 2; mi++)
#pragma unroll
        for (int hi = 0; hi < 2; hi++)
            qsc[mi * 2 + hi] = g_qs[mt * MT + wm + mi * 16 + (lane >> 2) + hi * 8];
    float qmax = fmaxf(fmaxf(qsc[0], qsc[1]), fmaxf(qsc[2], qsc[3]));

    float t[4][KSEL];
#pragma unroll
    for (int rr = 0; rr < 4; rr++)
#pragma unroll
        for (int i = 0; i < KSEL; i++) t[rr][i] = -1e30f;

    mbar_wait(sb + MB_QFULL, 0);

    int kk = 0;
    int cq = (lane & 3) * 2;
    for (int i = 0; i < nloc; i++) {
        int c = sp + i * SPLITS;
        int nv = NDB - c * NC; if (nv > NC) nv = NC;
        int acc[2][8][4];
#pragma unroll
        for (int mi = 0; mi < 2; mi++)
#pragma unroll
            for (int nt = 0; nt < 8; nt++)
#pragma unroll
                for (int r = 0; r < 4; r++) acc[mi][nt][r] = 0;

        for (int j = 0; j < NKSUB; j++, kk++) {
            int s = kk & (NSTAGE - 1);
            mbar_wait(sb + MB_DBFULL(s), (kk >> 3) & 1);
            uint32_t qs0 = qb0 + (uint32_t)j * TILE_BYTES;
            uint32_t qs1 = qb1 + (uint32_t)j * TILE_BYTES;
            uint32_t dbs = sb + SM_DB + (uint32_t)s * TILE_BYTES + dbrow;
#pragma unroll
            for (int k2 = 0; k2 < 4; k2++) {
                uint32_t coA = ((uint32_t)(k2 * 32) + a_k2) ^ xm;
                uint32_t coB = ((uint32_t)(k2 * 32) + b_k2) ^ xm;
                uint32_t a[2][4];
                ldsm_x4(a[0], qs0 + coA);
                ldsm_x4(a[1], qs1 + coA);
#pragma unroll
                for (int g = 0; g < 4; g++) {
                    uint32_t b[4];
                    ldsm_x4(b, dbs + (uint32_t)(g * 16 * 128) + coB);
                    mma16832_s8(acc[0][g * 2 + 0], a[0], b[0], b[1]);
                    mma16832_s8(acc[1][g * 2 + 0], a[1], b[0], b[1]);
                    mma16832_s8(acc[0][g * 2 + 1], a[0], b[2], b[3]);
                    mma16832_s8(acc[1][g * 2 + 1], a[1], b[2], b[3]);
                }
            }
            if (elect1()) mbar_arrive(sb + MB_DBDONE(s));
        }

        // -------- epilogue: dequant + fold with int-domain group prune --------
        const float* xsb = (const float*)(smem + SM_SCALE + (i & 3) * 512);
        float xs[16];
        float sxm = 0.f;
#pragma unroll
        for (int nt = 0; nt < 8; nt++)
#pragma unroll
            for (int h = 0; h < 2; h++) {
                xs[nt * 2 + h] = xsb[wn + nt * 8 + cq + h];
                sxm = fmaxf(sxm, xs[nt * 2 + h]);
            }
        float smax = sxm * qmax;
        float tmin = fminf(fminf(t[0][KSEL - 1], t[1][KSEL - 1]),
                           fminf(t[2][KSEL - 1], t[3][KSEL - 1]));
        // Prune soundness:
        //  - im >= 0: for acc>=0, acc*qsc*xs <= im*smax <= thr; acc<0 values negative < thr
        //  - im <  0: im*smax <= 0 < thr triggers prune; all values negative < thr
        //  - thr <= 0: prune disabled (thrEff = -1e30 forces slow path)
        float thrEff = (tmin > 0.f) ? tmin : -1e30f;

        if (nv == NC) {
#pragma unroll
            for (int mi = 0; mi < 2; mi++)
#pragma unroll
                for (int nt = 0; nt < 8; nt++) {
                    int im = max(max(acc[mi][nt][0], acc[mi][nt][1]),
                                 max(acc[mi][nt][2], acc[mi][nt][3]));
                    if ((float)im * smax > thrEff) {  // slow path: rare after warm-up
#pragma unroll
                        for (int r = 0; r < 4; r++) {
                            float v = (float)acc[mi][nt][r] * qsc[mi * 2 + (r >> 1)] * xs[nt * 2 + (r & 1)];
                            topk_insert(t[mi * 2 + (r >> 1)], v);
                        }
                    }
                }
        } else {
#pragma unroll
            for (int mi = 0; mi < 2; mi++)
#pragma unroll
                for (int nt = 0; nt < 8; nt++)
#pragma unroll
                    for (int r = 0; r < 4; r++) {
                        int col = wn + nt * 8 + cq + (r & 1);
                        if (col < nv) {
                            float v = (float)acc[mi][nt][r] * qsc[mi * 2 + (r >> 1)] * xs[nt * 2 + (r & 1)];
                            topk_insert(t[mi * 2 + (r >> 1)], v);
                        }
                    }
        }
    }

    // -------- CTA-level reduce: 8 lists/row -> 1 list/row --------
    asm volatile("bar.sync 1, 256;" ::: "memory");  // compute warps only
    float* lists = (float*)(smem + SM_Q);           // dead Q smem (40 KB used)
    {
        int listid = (wid & 1) * 4 + (lane & 3);
#pragma unroll
        for (int mi = 0; mi < 2; mi++)
#pragma unroll
            for (int hi = 0; hi < 2; hi++) {
                int row = wm + mi * 16 + (lane >> 2) + hi * 8;
                float* p = lists + (row * NLIST + listid) * KSEL;
#pragma unroll
                for (int i = 0; i < KSEL; i++) p[i] = t[mi * 2 + hi][i];
            }
    }
    asm volatile("bar.sync 1, 256;" ::: "memory");
    if (tid < MT) {
        float f[KSEL];
#pragma unroll
        for (int i = 0; i < KSEL; i++) f[i] = -1e30f;
        const float* p = lists + tid * NLIST * KSEL;
        for (int l = 0; l < NLIST * KSEL; l++) topk_insert(f, p[l]);
        float* outp = g_topk + (((size_t)mt * SPLITS + sp) * MT + tid) * KSEL;
#pragma unroll
        for (int i = 0; i < KSEL; i++) outp[i] = f[i];
    }
}

// ---------------- merge: one WARP per query folds SPLITS sorted top-10 lists ----------------
__global__ void knn_merge_kernel(float* __restrict__ out) {
    int gw = (blockIdx.x * blockDim.x + threadIdx.x) >> 5;
    int lane = threadIdx.x & 31;
    if (gw >= NMT * MT) return;
    int mtile = gw >> 7, tr = gw & 127;

    float t[KSEL];
#pragma unroll
    for (int i = 0; i < KSEL; i++) t[i] = -1e30f;
    for (int v = lane; v < SPLITS * KSEL; v += 32) {
        int s = v / KSEL, i = v - s * KSEL;
        float x = g_topk[(((size_t)mtile * SPLITS + s) * MT + tr) * KSEL + i];
        topk_insert(t, x);
    }
#pragma unroll
    for (int off = 16; off; off >>= 1) {  // butterfly: lane^off always valid
        float o[KSEL];
#pragma unroll
        for (int i = 0; i < KSEL; i++) o[i] = __shfl_xor_sync(0xffffffffu, t[i], off);
#pragma unroll
        for (int i = 0; i < KSEL; i++) topk_insert(t, o[i]);
    }
    if (lane == 0) out[gw] = 2.0f - 2.0f * t[KSEL - 1];
}

// ---------------- launch ----------------
extern "C" void kernel_launch(void* const* d_in, const int* in_sizes, int n_in,
                              void* d_out, int out_size) {
    const float* features = (const float*)d_in[0];
    // d_in[1] = logits (unused), d_in[3] = k (fixed 10)
    const float* db = (const float*)d_in[2];
    float* out = (float*)d_out;

    cudaFuncSetAttribute(knn_gemm_kernel, cudaFuncAttributeMaxDynamicSharedMemorySize, SMEM_TOTAL);

    knn_prep_kernel<<<(2048 + 7) / 8, 256>>>(features, 0, 2048, 2048);
    knn_prep_kernel<<<(NDB_PAD + 7) / 8, 256>>>(db, 1, NDB_PAD, NDB);
    knn_gemm_kernel<<<dim3(NMT, SPLITS), 288, SMEM_TOTAL>>>();
    knn_merge_kernel<<<(NMT * MT * 32 + 255) / 256, 256>>>(out);
}

// round 15
// speedup vs baseline: 1.1599x; 1.1599x over previous
#include <cuda_runtime.h>
#include <cuda_bf16.h>
#include <stdint.h>

// ---------------- problem constants ----------------
#define DV      512
#define NKSUB   4            // 512 / 128 int8 k-subtiles
#define MT      64           // query rows per m-tile (R15: halved for 2 CTAs/SM)
#define NMT2    32           // 2048 / 64
#define NC      128          // db rows per chunk
#define NCHUNK  782          // ceil(100000/128)
#define NDB     100000
#define NDB_PAD (NCHUNK * NC)
#define SPLITS  18           // 32*18 = 576 CTAs = 2 waves of 296 (2 CTAs/SM)
#define KSEL    10
#define QT_BYTES   8192      // [64 rows x 128 k] int8 Q subtile, SW128
#define TILE_BYTES 16384     // [128 rows x 128 k] int8 DB subtile, SW128
#define NLIST   16           // per-row partial lists inside a CTA (4 n-warps x 4 lane-cols)

// smem layout (per CTA ~99 KB -> 2 CTAs/SM)
#define SM_MBAR    0
#define SM_SCALE   1024                              // 4 x 512 B db-scale ring
#define SM_Q       3072                              // 4 x 8 KB = 32 KB
#define SM_DB      (SM_Q + NKSUB * QT_BYTES)         // 35840
#define NSTAGE     4
#define SMEM_TOTAL (SM_DB + NSTAGE * TILE_BYTES)     // 101376 (~99 KB; 2 per SM)

#define MB_DBFULL(s)  (SM_MBAR + 8 * (s))
#define MB_DBDONE(s)  (SM_MBAR + 64 + 8 * (s))
#define MB_QFULL      (SM_MBAR + 128)

// ---------------- global scratch (no allocs allowed) ----------------
__device__ __align__(1024) unsigned char g_qn[(size_t)NMT2 * NKSUB * QT_BYTES];       // 1 MB int8
__device__ __align__(1024) unsigned char g_dbn[(size_t)NCHUNK * NKSUB * TILE_BYTES];  // ~51 MB int8
__device__ float g_qs[NMT2 * MT];                                                     // q row scales
__device__ __align__(16) float g_dbs[NDB_PAD];                                        // db row scales
__device__ float g_topk[(size_t)NMT2 * SPLITS * MT * KSEL];                           // 1.5 MB

// ---------------- PTX helpers (base-sm_100-safe; no tcgen05) ----------------
__device__ __forceinline__ uint32_t smem_u32(const void* p) {
    return (uint32_t)__cvta_generic_to_shared(p);
}
__device__ __forceinline__ uint32_t elect1() {
    uint32_t p;
    asm volatile("{\n\t.reg .pred P;\n\telect.sync _|P, 0xffffffff;\n\tselp.b32 %0,1,0,P;\n\t}" : "=r"(p));
    return p;
}
__device__ __forceinline__ void mbar_init(uint32_t a, uint32_t cnt) {
    asm volatile("mbarrier.init.shared.b64 [%0], %1;" :: "r"(a), "r"(cnt) : "memory");
}
__device__ __forceinline__ void mbar_expect_tx(uint32_t a, uint32_t bytes) {
    asm volatile("mbarrier.arrive.expect_tx.shared.b64 _, [%0], %1;" :: "r"(a), "r"(bytes) : "memory");
}
__device__ __forceinline__ void mbar_arrive(uint32_t a) {
    asm volatile("mbarrier.arrive.shared.b64 _, [%0];" :: "r"(a) : "memory");
}
__device__ __forceinline__ void mbar_wait(uint32_t a, uint32_t parity) {
    asm volatile(
        "{\n\t.reg .pred P;\n"
        "WL%=:\n\t"
        "mbarrier.try_wait.parity.acquire.cta.shared::cta.b64 P, [%0], %1, 0x989680;\n\t"
        "@P bra.uni WD%=;\n\t"
        "bra.uni WL%=;\n"
        "WD%=:\n\t}"
        :: "r"(a), "r"(parity) : "memory");
}
__device__ __forceinline__ void bulk_g2s(uint32_t dst, const void* src, uint32_t bytes, uint32_t mbar) {
    asm volatile(
        "cp.async.bulk.shared::cluster.global.mbarrier::complete_tx::bytes [%0], [%1], %2, [%3];"
        :: "r"(dst), "l"(src), "r"(bytes), "r"(mbar) : "memory");
}
__device__ __forceinline__ void ldsm_x4(uint32_t* r, uint32_t addr) {
    asm volatile("ldmatrix.sync.aligned.m8n8.x4.shared.b16 {%0,%1,%2,%3}, [%4];"
                 : "=r"(r[0]), "=r"(r[1]), "=r"(r[2]), "=r"(r[3]) : "r"(addr));
}
// int8 mma: m16n8k32.s8 fragments are byte-identical to m16n8k16.b16 fragments.
__device__ __forceinline__ void mma16832_s8(int* d, const uint32_t* a, uint32_t b0, uint32_t b1) {
    asm volatile(
        "mma.sync.aligned.m16n8k32.row.col.s32.s8.s8.s32 "
        "{%0,%1,%2,%3}, {%4,%5,%6,%7}, {%8,%9}, {%0,%1,%2,%3};"
        : "+r"(d[0]), "+r"(d[1]), "+r"(d[2]), "+r"(d[3])
        : "r"(a[0]), "r"(a[1]), "r"(a[2]), "r"(a[3]), "r"(b0), "r"(b1));
}

__device__ __forceinline__ void topk_insert(float (&t)[KSEL], float v) {
    if (v > t[KSEL - 1]) {
        t[KSEL - 1] = v;
#pragma unroll
        for (int i = KSEL - 1; i > 0; --i) {
            if (t[i] > t[i - 1]) { float tmp = t[i - 1]; t[i - 1] = t[i]; t[i] = tmp; }
        }
    }
}

// ---------------- prep: normalize + per-row int8 quantize, tiled + SW128 pre-swizzled ----------------
// which: 0 = queries (64-row tiles), 1 = db (128-row tiles). One warp per row.
__global__ void knn_prep_kernel(const float* __restrict__ src, int which,
                                int rows_pad, int rows_valid) {
    int gw = (blockIdx.x * blockDim.x + threadIdx.x) >> 5;
    int lane = threadIdx.x & 31;
    if (gw >= rows_pad) return;

    unsigned char* dst;
    {
        int tile, tr, sub;
        unsigned char* base;
        if (which) { tile = gw >> 7; tr = gw & 127; sub = TILE_BYTES; base = g_dbn; }
        else       { tile = gw >> 6; tr = gw & 63;  sub = QT_BYTES;   base = g_qn;  }
        int c0 = lane * 16;
        int ks = c0 >> 7;
        uint32_t off = (uint32_t)(tr * 128 + (c0 & 127));
        off ^= (off >> 3) & 0x70;     // SW128
        dst = base + (size_t)tile * (NKSUB * sub) + (size_t)ks * sub + off;
    }

    if (gw >= rows_valid) {           // zero pad (db only)
        *(uint4*)dst = make_uint4(0u, 0u, 0u, 0u);
        if (lane == 0) g_dbs[gw] = 0.f;
        return;
    }

    const float4* row = (const float4*)(src + (size_t)gw * DV);
    float4 v[4];
    float ss = 0.f, am = 0.f;
#pragma unroll
    for (int i = 0; i < 4; i++) {
        v[i] = row[i * 32 + lane];
        ss += v[i].x * v[i].x + v[i].y * v[i].y + v[i].z * v[i].z + v[i].w * v[i].w;
        am = fmaxf(am, fmaxf(fmaxf(fabsf(v[i].x), fabsf(v[i].y)), fmaxf(fabsf(v[i].z), fabsf(v[i].w))));
    }
#pragma unroll
    for (int o = 16; o; o >>= 1) {
        ss += __shfl_xor_sync(0xffffffffu, ss, o);
        am = fmaxf(am, __shfl_xor_sync(0xffffffffu, am, o));
    }
    float rn = rsqrtf(ss);
    rn = rn * (1.5f - 0.5f * ss * rn * rn);
    float inv = 127.0f / fmaxf(am, 1e-20f);

    uint32_t w[4];
#pragma unroll
    for (int i = 0; i < 4; i++) {
        int q0 = __float2int_rn(v[i].x * inv);
        int q1 = __float2int_rn(v[i].y * inv);
        int q2 = __float2int_rn(v[i].z * inv);
        int q3 = __float2int_rn(v[i].w * inv);
        w[i] = (q0 & 0xff) | ((q1 & 0xff) << 8) | ((q2 & 0xff) << 16) | ((q3 & 0xff) << 24);
    }
    *(uint4*)dst = make_uint4(w[0], w[1], w[2], w[3]);
    if (lane == 0) {
        float sc = am * rn / 127.0f;
        if (which) g_dbs[gw] = sc; else g_qs[gw] = sc;
    }
}

// ---------------- main GEMM (mma.sync s8) + fused streaming top-k ----------------
// grid (NMT2, SPLITS), 288 threads, 2 CTAs/SM: warps 0-7 compute (2m x 4n,
// warp tile 32x32), warp 8 producer. Fold is the R11 unconditional one (prune reverted).
__global__ void __launch_bounds__(288, 2) knn_gemm_kernel() {
    extern __shared__ unsigned char smem[];
    uint32_t sb = smem_u32(smem);
    int tid = threadIdx.x;
    int wid = tid >> 5;
    int lane = tid & 31;
    int mt = blockIdx.x;
    int sp = blockIdx.y;
    int nloc = (NCHUNK - sp + SPLITS - 1) / SPLITS;

    if (tid == 0) {
#pragma unroll
        for (int s = 0; s < NSTAGE; s++) { mbar_init(sb + MB_DBFULL(s), 1); mbar_init(sb + MB_DBDONE(s), 8); }
        mbar_init(sb + MB_QFULL, 1);
    }
    __syncthreads();

    if (wid == 8) {
        // -------- producer --------
        if (elect1()) {
            const unsigned char* qg = g_qn + (size_t)mt * (NKSUB * QT_BYTES);
            mbar_expect_tx(sb + MB_QFULL, NKSUB * QT_BYTES);
#pragma unroll
            for (int j = 0; j < NKSUB; j++)
                bulk_g2s(sb + SM_Q + j * QT_BYTES, qg + (size_t)j * QT_BYTES, QT_BYTES, sb + MB_QFULL);
            int kk = 0;
            for (int i = 0; i < nloc; i++) {
                int c = sp + i * SPLITS;
                const unsigned char* dg = g_dbn + (size_t)c * (NKSUB * TILE_BYTES);
                for (int j = 0; j < NKSUB; j++, kk++) {
                    int s = kk & (NSTAGE - 1);
                    if (kk >= NSTAGE) mbar_wait(sb + MB_DBDONE(s), ((kk >> 2) & 1) ^ 1);
                    mbar_expect_tx(sb + MB_DBFULL(s), TILE_BYTES + (j == 0 ? 512 : 0));
                    bulk_g2s(sb + SM_DB + s * TILE_BYTES, dg + (size_t)j * TILE_BYTES, TILE_BYTES,
                             sb + MB_DBFULL(s));
                    if (j == 0)  // chunk's 128 db row scales (slot reuse distance = 4 chunks, safe)
                        bulk_g2s(sb + SM_SCALE + (i & 3) * 512, g_dbs + c * NC, 512, sb + MB_DBFULL(s));
                }
            }
        }
        return;
    }

    // -------- compute warps: 2m x 4n, warp tile 32x32 --------
    int wm = (wid >> 2) * 32;           // m-slab base (0, 32)
    int wn = (wid & 3) * 32;            // n-slab base (0, 32, 64, 96)
    int mat = lane >> 3, mrow = lane & 7;
    uint32_t xm = (uint32_t)(mrow * 16);                 // SW128 xor mask
    int a_r0 = wm + (mat & 1) * 8 + mrow;
    uint32_t a_k2 = (uint32_t)((mat >> 1) * 16);
    uint32_t qb0 = sb + SM_Q + (uint32_t)(a_r0 * 128);
    uint32_t qb1 = qb0 + 16 * 128;                       // mi=1 (+16 rows, < 64)
    int b_n = wn + (mat >> 1) * 8 + mrow;
    uint32_t b_k2 = (uint32_t)((mat & 1) * 16);
    uint32_t dbrow = (uint32_t)(b_n * 128);

    // q row scales for this thread's 4 owned rows
    float qsc[4];
#pragma unroll
    for (int mi = 0; mi < 2; mi++)
#pragma unroll
        for (int hi = 0; hi < 2; hi++)
            qsc[mi * 2 + hi] = g_qs[mt * MT + wm + mi * 16 + (lane >> 2) + hi * 8];

    float t[4][KSEL];
#pragma unroll
    for (int rr = 0; rr < 4; rr++)
#pragma unroll
        for (int i = 0; i < KSEL; i++) t[rr][i] = -1e30f;

    mbar_wait(sb + MB_QFULL, 0);

    int kk = 0;
    int cq = (lane & 3) * 2;
    for (int i = 0; i < nloc; i++) {
        int c = sp + i * SPLITS;
        int nv = NDB - c * NC; if (nv > NC) nv = NC;
        int acc[2][4][4];
#pragma unroll
        for (int mi = 0; mi < 2; mi++)
#pragma unroll
            for (int nt = 0; nt < 4; nt++)
#pragma unroll
                for (int r = 0; r < 4; r++) acc[mi][nt][r] = 0;

        for (int j = 0; j < NKSUB; j++, kk++) {
            int s = kk & (NSTAGE - 1);
            mbar_wait(sb + MB_DBFULL(s), (kk >> 2) & 1);
            uint32_t qs0 = qb0 + (uint32_t)j * QT_BYTES;
            uint32_t qs1 = qb1 + (uint32_t)j * QT_BYTES;
            uint32_t dbs = sb + SM_DB + (uint32_t)s * TILE_BYTES + dbrow;
#pragma unroll
            for (int k2 = 0; k2 < 4; k2++) {
                uint32_t coA = ((uint32_t)(k2 * 32) + a_k2) ^ xm;
                uint32_t coB = ((uint32_t)(k2 * 32) + b_k2) ^ xm;
                uint32_t a[2][4];
                ldsm_x4(a[0], qs0 + coA);
                ldsm_x4(a[1], qs1 + coA);
#pragma unroll
                for (int g = 0; g < 2; g++) {
                    uint32_t b[4];
                    ldsm_x4(b, dbs + (uint32_t)(g * 16 * 128) + coB);
                    mma16832_s8(acc[0][g * 2 + 0], a[0], b[0], b[1]);
                    mma16832_s8(acc[1][g * 2 + 0], a[1], b[0], b[1]);
                    mma16832_s8(acc[0][g * 2 + 1], a[0], b[2], b[3]);
                    mma16832_s8(acc[1][g * 2 + 1], a[1], b[2], b[3]);
                }
            }
            if (elect1()) mbar_arrive(sb + MB_DBDONE(s));
        }

        // -------- epilogue: dequant + fold (unconditional; prune reverted) --------
        const float* xsb = (const float*)(smem + SM_SCALE + (i & 3) * 512);
        float xs[8];
#pragma unroll
        for (int nt = 0; nt < 4; nt++)
#pragma unroll
            for (int h = 0; h < 2; h++)
                xs[nt * 2 + h] = xsb[wn + nt * 8 + cq + h];

        if (nv == NC) {
#pragma unroll
            for (int mi = 0; mi < 2; mi++)
#pragma unroll
                for (int nt = 0; nt < 4; nt++)
#pragma unroll
                    for (int r = 0; r < 4; r++) {
                        float v = (float)acc[mi][nt][r] * qsc[mi * 2 + (r >> 1)] * xs[nt * 2 + (r & 1)];
                        topk_insert(t[mi * 2 + (r >> 1)], v);
                    }
        } else {
#pragma unroll
            for (int mi = 0; mi < 2; mi++)
#pragma unroll
                for (int nt = 0; nt < 4; nt++)
#pragma unroll
                    for (int r = 0; r < 4; r++) {
                        int col = wn + nt * 8 + cq + (r & 1);
                        if (col < nv) {
                            float v = (float)acc[mi][nt][r] * qsc[mi * 2 + (r >> 1)] * xs[nt * 2 + (r & 1)];
                            topk_insert(t[mi * 2 + (r >> 1)], v);
                        }
                    }
        }
    }

    // -------- CTA-level reduce: 16 lists/row -> 1 list/row --------
    asm volatile("bar.sync 1, 256;" ::: "memory");  // compute warps only (producer exited)
    // Stage lists into dead Q smem (+ dead first DB stage): [row][16][KSEL] = 40 KB
    float* lists = (float*)(smem + SM_Q);
    {
        int listid = (wid & 3) * 4 + (lane & 3);
#pragma unroll
        for (int mi = 0; mi < 2; mi++)
#pragma unroll
            for (int hi = 0; hi < 2; hi++) {
                int row = wm + mi * 16 + (lane >> 2) + hi * 8;
                float* p = lists + (row * NLIST + listid) * KSEL;
#pragma unroll
                for (int i = 0; i < KSEL; i++) p[i] = t[mi * 2 + hi][i];
            }
    }
    asm volatile("bar.sync 1, 256;" ::: "memory");
    if (tid < MT) {
        float f[KSEL];
#pragma unroll
        for (int i = 0; i < KSEL; i++) f[i] = -1e30f;
        const float* p = lists + tid * NLIST * KSEL;
        for (int l = 0; l < NLIST * KSEL; l++) topk_insert(f, p[l]);
        float* outp = g_topk + (((size_t)mt * SPLITS + sp) * MT + tid) * KSEL;
#pragma unroll
        for (int i = 0; i < KSEL; i++) outp[i] = f[i];
    }
}

// ---------------- merge: one WARP per query folds SPLITS sorted top-10 lists ----------------
__global__ void knn_merge_kernel(float* __restrict__ out) {
    int gw = (blockIdx.x * blockDim.x + threadIdx.x) >> 5;
    int lane = threadIdx.x & 31;
    if (gw >= NMT2 * MT) return;
    int mtile = gw >> 6, tr = gw & 63;

    float t[KSEL];
#pragma unroll
    for (int i = 0; i < KSEL; i++) t[i] = -1e30f;
    for (int v = lane; v < SPLITS * KSEL; v += 32) {
        int s = v / KSEL, i = v - s * KSEL;
        float x = g_topk[(((size_t)mtile * SPLITS + s) * MT + tr) * KSEL + i];
        topk_insert(t, x);
    }
#pragma unroll
    for (int off = 16; off; off >>= 1) {  // butterfly: lane^off always valid
        float o[KSEL];
#pragma unroll
        for (int i = 0; i < KSEL; i++) o[i] = __shfl_xor_sync(0xffffffffu, t[i], off);
#pragma unroll
        for (int i = 0; i < KSEL; i++) topk_insert(t, o[i]);
    }
    if (lane == 0) out[gw] = 2.0f - 2.0f * t[KSEL - 1];
}

// ---------------- launch ----------------
extern "C" void kernel_launch(void* const* d_in, const int* in_sizes, int n_in,
                              void* d_out, int out_size) {
    const float* features = (const float*)d_in[0];
    // d_in[1] = logits (unused), d_in[3] = k (fixed 10)
    const float* db = (const float*)d_in[2];
    float* out = (float*)d_out;

    cudaFuncSetAttribute(knn_gemm_kernel, cudaFuncAttributeMaxDynamicSharedMemorySize, SMEM_TOTAL);

    knn_prep_kernel<<<(2048 + 7) / 8, 256>>>(features, 0, 2048, 2048);
    knn_prep_kernel<<<(NDB_PAD + 7) / 8, 256>>>(db, 1, NDB_PAD, NDB);
    knn_gemm_kernel<<<dim3(NMT2, SPLITS), 288, SMEM_TOTAL>>>();
    knn_merge_kernel<<<(NMT2 * MT * 32 + 255) / 256, 256>>>(out);
}